// round 2
// baseline (speedup 1.0000x reference)
#include <cuda_runtime.h>
#include <math.h>

#define NB    8
#define NQd   32
#define NEq   256
#define SSq   21
#define NSTEP 20
#define DDim  256
#define HHn   8
#define HDn   32
#define LLn   4
#define PPn   4
#define VVn   10000
#define TTn   1920

// ------------------------- device scratch (no allocation allowed) -------------------------
__device__ __align__(16) float g_value [NB*HHn*TTn*HDn];   // [b][h][t][hd]
__device__ __align__(16) float g_mixp  [4*NEq*512];        // split-K partials: off|aw|hbias
__device__ __align__(16) float g_gatesp[4*NEq*1024];       // split-K partials: gates
__device__ __align__(16) float g_logits[NEq*VVn];
__device__ __align__(16) float g_hq    [NEq*512];          // [h | query]
__device__ __align__(16) float g_xh    [NEq*1024];         // [emb | attn_res | query | h]
__device__ __align__(16) float g_h     [NEq*DDim];
__device__ __align__(16) float g_c     [NEq*DDim];
__device__ __align__(16) float g_bigw  [512*512];          // cols: off(128)|aw(128)|hs_w(256, rows<256)
__device__ __align__(16) float g_bigb  [512];
__device__ __align__(16) float g_gatew [1024*1024];        // rows: wih(768) ; whh(256)

__device__ __forceinline__ float tanha(float x) {
    float y;
    asm("tanh.approx.f32 %0, %1;" : "=f"(y) : "f"(x));
    return y;
}

// ------------------------- generic 64x64 tiled fp32 GEMM -------------------------
// C[m,n] = sum_k A[m,k]*W[k,n] (+bias). MODE 0: plain row-major out (+ split-K partial
// stride via blockIdx.z). MODE 1: value build: out = (acc+bias)*mask, scattered to
// g_value[b][h][t][hd] layout.
template<int MODE>
__global__ __launch_bounds__(256)
void gemm64(const float* __restrict__ A, int lda,
            const float* __restrict__ W, int ldw,
            const float* __restrict__ bias,
            float* __restrict__ C,
            int N, int kChunk, int partStride,
            const float* __restrict__ mask)
{
    __shared__ float As[16*68];   // padded stride 68 to cut STS conflicts
    __shared__ float Bs[16*64];

    const int tid  = threadIdx.x;
    const int tx   = tid & 15;
    const int ty   = tid >> 4;
    const int col0 = blockIdx.x * 64;
    const int row0 = blockIdx.y * 64;
    const int kbeg = blockIdx.z * kChunk;
    const int kend = kbeg + kChunk;

    float acc[4][4];
#pragma unroll
    for (int i = 0; i < 4; i++)
#pragma unroll
        for (int j = 0; j < 4; j++) acc[i][j] = 0.f;

    const int ar = tid >> 2;          // 0..63 row within tile
    const int ak = (tid & 3) << 2;    // 0,4,8,12
    const int bk = tid >> 4;          // 0..15
    const int bc = (tid & 15) << 2;   // 0..60

    for (int k0 = kbeg; k0 < kend; k0 += 16) {
        // A tile (M,K always multiples of tile — no guards needed)
        float4 av = *(const float4*)(A + (size_t)(row0 + ar) * lda + (k0 + ak));
        As[(ak+0)*68 + ar] = av.x;
        As[(ak+1)*68 + ar] = av.y;
        As[(ak+2)*68 + ar] = av.z;
        As[(ak+3)*68 + ar] = av.w;
        // B tile (guard N edge)
        {
            const float* wr = W + (size_t)(k0 + bk) * ldw;
            int wc = col0 + bc;
            float4 bv;
            if (wc + 3 < N) {
                bv = *(const float4*)(wr + wc);
            } else {
                bv.x = (wc     < N) ? wr[wc]     : 0.f;
                bv.y = (wc + 1 < N) ? wr[wc + 1] : 0.f;
                bv.z = (wc + 2 < N) ? wr[wc + 2] : 0.f;
                bv.w = (wc + 3 < N) ? wr[wc + 3] : 0.f;
            }
            *(float4*)(Bs + bk*64 + bc) = bv;
        }
        __syncthreads();
#pragma unroll
        for (int k = 0; k < 16; k++) {
            float4 a = *(const float4*)(As + k*68 + (ty << 2));
            float4 b = *(const float4*)(Bs + k*64 + (tx << 2));
            float a4[4] = {a.x, a.y, a.z, a.w};
            float b4[4] = {b.x, b.y, b.z, b.w};
#pragma unroll
            for (int i = 0; i < 4; i++)
#pragma unroll
                for (int j = 0; j < 4; j++)
                    acc[i][j] = fmaf(a4[i], b4[j], acc[i][j]);
        }
        __syncthreads();
    }

    if (MODE == 0) {
#pragma unroll
        for (int i = 0; i < 4; i++) {
            int m = row0 + (ty << 2) + i;
            size_t base = (size_t)blockIdx.z * partStride + (size_t)m * N;
#pragma unroll
            for (int j = 0; j < 4; j++) {
                int nc = col0 + (tx << 2) + j;
                if (nc < N) C[base + nc] = acc[i][j] + (bias ? bias[nc] : 0.f);
            }
        }
    } else {
        // value build: m = b*T + t ; n = h*32 + hd
#pragma unroll
        for (int i = 0; i < 4; i++) {
            int m  = row0 + (ty << 2) + i;
            int b  = m / TTn;
            int t  = m - b * TTn;
            float mk = mask[m];
#pragma unroll
            for (int j = 0; j < 4; j++) {
                int nc = col0 + (tx << 2) + j;
                int h  = nc >> 5, hd = nc & 31;
                C[(((size_t)(b*HHn + h))*TTn + t)*HDn + hd] = (acc[i][j] + bias[nc]) * mk;
            }
        }
    }
}

// ------------------------- preamble kernels -------------------------
__global__ void build_bigw(const float* __restrict__ offw, const float* __restrict__ aww,
                           const float* __restrict__ hsw,  const float* __restrict__ offb,
                           const float* __restrict__ awb,  const float* __restrict__ hsb)
{
    int i = blockIdx.x * 256 + threadIdx.x;     // 0 .. 512*512-1
    int k = i >> 9, j = i & 511;
    float v;
    if (j < 128)      v = offw[k*128 + j];
    else if (j < 256) v = aww[k*128 + (j - 128)];
    else              v = (k < 256) ? hsw[k*256 + (j - 256)] : 0.f;
    g_bigw[i] = v;
    if (i < 512)
        g_bigb[i] = (i < 128) ? offb[i] : (i < 256) ? awb[i-128] : hsb[i-256];
}

__global__ void build_gatew(const float* __restrict__ wih, const float* __restrict__ whh)
{
    int i = blockIdx.x * 256 + threadIdx.x;     // 0 .. 1024*1024-1
    int k = i >> 10, j = i & 1023;
    g_gatew[i] = (k < 768) ? wih[k*1024 + j] : whh[(k - 768)*1024 + j];
}

__global__ void init_state(const float* __restrict__ query)
{
    int n = blockIdx.x, d = threadIdx.x;
    float q = query[n*DDim + d];
    g_h[n*DDim + d] = 0.f;
    g_c[n*DDim + d] = 0.f;
    g_hq[n*512 + d]        = 0.f;   // h slot
    g_hq[n*512 + 256 + d]  = q;     // query slot (static)
    g_xh[n*1024 + 512 + d] = q;     // query slot (static)
    g_xh[n*1024 + 768 + d] = 0.f;   // h slot
}

// ------------------------- fused MSDA + alpha + attn_res (block per query) -------------------------
__global__ __launch_bounds__(256)
void msda_step(const float* __restrict__ rp,     const float* __restrict__ vr,
               const int*   __restrict__ seq,    const float* __restrict__ embw,
               const float* __restrict__ ctxw,   const float* __restrict__ ctxb,
               const float* __restrict__ alphaw, const float* __restrict__ alphab,
               int step)
{
    __shared__ float s_hsamp[128*32];   // [h*16+lp][hd], aw-weighted samples
    __shared__ float s_hb[256];         // hbias + ctx_b
    __shared__ float s_off[128];
    __shared__ float s_aw[128];
    __shared__ float s_alpha[128];
    __shared__ float s_wgt[128];

    const int n    = blockIdx.x;
    const int b    = n >> 5;
    const int tid  = threadIdx.x;
    const int lane = tid & 31;
    const int w    = tid >> 5;

    // ---- phase A: emb write, gather split-K mix partials, aw softmax ----
    {
        int tok = (step == 0) ? 1 : seq[n*SSq + step - 1];
        g_xh[n*1024 + tid] = embw[(size_t)tok * DDim + tid];
    }
    {
        float s = 0.f;
#pragma unroll
        for (int z = 0; z < 4; z++) s += g_mixp[z*(NEq*512) + n*512 + 256 + tid];
        s_hb[tid] = s + g_bigb[256 + tid] + ctxb[tid];
    }
    if (tid < 128) {
        float so = 0.f, sa = 0.f;
#pragma unroll
        for (int z = 0; z < 4; z++) {
            so += g_mixp[z*(NEq*512) + n*512 + tid];
            sa += g_mixp[z*(NEq*512) + n*512 + 128 + tid];
        }
        so += g_bigb[tid];
        sa += g_bigb[128 + tid];
        s_off[tid] = so;
        float m = sa;
#pragma unroll
        for (int o = 8; o; o >>= 1) m = fmaxf(m, __shfl_xor_sync(0xffffffffu, m, o));
        float e = __expf(sa - m);
        float sm = e;
#pragma unroll
        for (int o = 8; o; o >>= 1) sm += __shfl_xor_sync(0xffffffffu, sm, o);
        s_aw[tid] = e / sm;
    }
    __syncthreads();

    // ---- phase B: bilinear sampling (warp w -> combos 16w..16w+15, lane = hd) ----
    {
        const float rpn = rp[n];
#pragma unroll
        for (int i = 0; i < 16; i++) {
            int r = (w << 4) + i;
            int h = r >> 4;
            int l = (r >> 2) & 3;
            int shape_l = 1024 >> l;
            int start_l = 2048 - (2048 >> l);
            float refl = rpn * vr[b*LLn + l];
            float x = refl * (float)shape_l + s_off[r] - 0.5f;
            float x0f = floorf(x);
            float wf = x - x0f;
            int x0 = (int)x0f;
            const float* vbase = g_value + (((size_t)(b*HHn + h))*TTn + start_l) * HDn;
            float g0 = (x0 >= 0     && x0     < shape_l) ? vbase[(size_t)x0      * HDn + lane] : 0.f;
            float g1 = (x0 + 1 >= 0 && x0 + 1 < shape_l) ? vbase[(size_t)(x0+1) * HDn + lane] : 0.f;
            s_hsamp[r*32 + lane] = (g0 * (1.f - wf) + g1 * wf) * s_aw[r];
        }
    }
    __syncthreads();

    // ---- phase C: alpha[row] = sum_d tanh(hsamp_row.ctx[:,d] + hb[d]) * alpha_w[d] ----
    {
        const int d0 = lane << 3;
        float aw8[8];
#pragma unroll
        for (int j = 0; j < 8; j++) aw8[j] = __ldg(&alphaw[d0 + j]);
        const float ab = alphab[0];

#pragma unroll
        for (int pass = 0; pass < 2; pass++) {
            int r0 = (w << 4) + (pass << 3);
            float acc[8][8];
#pragma unroll
            for (int j = 0; j < 8; j++) {
                float base = s_hb[d0 + j];
#pragma unroll
                for (int i = 0; i < 8; i++) acc[i][j] = base;
            }
#pragma unroll 2
            for (int k = 0; k < 32; k++) {
                float4 c0 = __ldg((const float4*)(ctxw + k*DDim + d0));
                float4 c1 = __ldg((const float4*)(ctxw + k*DDim + d0 + 4));
                float cj[8] = {c0.x, c0.y, c0.z, c0.w, c1.x, c1.y, c1.z, c1.w};
#pragma unroll
                for (int i = 0; i < 8; i++) {
                    float a = s_hsamp[(r0 + i)*32 + k];
#pragma unroll
                    for (int j = 0; j < 8; j++) acc[i][j] = fmaf(a, cj[j], acc[i][j]);
                }
            }
#pragma unroll
            for (int i = 0; i < 8; i++) {
                float part = 0.f;
#pragma unroll
                for (int j = 0; j < 8; j++) part = fmaf(tanha(acc[i][j]), aw8[j], part);
#pragma unroll
                for (int o = 16; o; o >>= 1) part += __shfl_xor_sync(0xffffffffu, part, o);
                if (lane == 0) s_alpha[r0 + i] = part + ab;
            }
        }
    }
    __syncthreads();

    // ---- phase D: softmax over 16 per head ----
    if (tid < 128) {
        float v = s_alpha[tid];
        float m = v;
#pragma unroll
        for (int o = 8; o; o >>= 1) m = fmaxf(m, __shfl_xor_sync(0xffffffffu, m, o));
        float e = __expf(v - m);
        float sm = e;
#pragma unroll
        for (int o = 8; o; o >>= 1) sm += __shfl_xor_sync(0xffffffffu, sm, o);
        s_wgt[tid] = e / sm;
    }
    __syncthreads();

    // ---- phase E: attn_res[h*32+hd] = sum_lp wgt * hsamp ----
    {
        int h = tid >> 5, hd = tid & 31;
        float res = 0.f;
#pragma unroll
        for (int lp = 0; lp < 16; lp++)
            res = fmaf(s_wgt[(h << 4) + lp], s_hsamp[((h << 4) + lp)*32 + hd], res);
        g_xh[n*1024 + 256 + tid] = res;
    }
}

// ------------------------- LSTM cell update (sums gate split-K partials) -------------------------
__global__ __launch_bounds__(256)
void lstm_update()
{
    int n = blockIdx.x, d = threadIdx.x;
    float gi = 0.f, gf = 0.f, gg = 0.f, go = 0.f;
#pragma unroll
    for (int z = 0; z < 4; z++) {
        const float* g = g_gatesp + (size_t)z*(NEq*1024) + n*1024;
        gi += g[d]; gf += g[256 + d]; gg += g[512 + d]; go += g[768 + d];
    }
    float c  = g_c[n*DDim + d];
    float sf = 1.f / (1.f + expf(-gf));
    float si = 1.f / (1.f + expf(-gi));
    float so = 1.f / (1.f + expf(-go));
    float c2 = sf * c + si * tanhf(gg);
    float h2 = so * tanhf(c2);
    g_c[n*DDim + d] = c2;
    g_h[n*DDim + d] = h2;
    g_hq[n*512 + d] = h2;
    g_xh[n*1024 + 768 + d] = h2;
}

// ------------------------- log-softmax over V, write output slice -------------------------
__global__ __launch_bounds__(256)
void logsoftmax_out(float* __restrict__ out, int step)
{
    __shared__ float sred[8];
    const int n = blockIdx.x, tid = threadIdx.x;
    const float* row = g_logits + (size_t)n * VVn;

    float m = -1e30f;
    for (int v = tid; v < VVn; v += 256) m = fmaxf(m, row[v]);
#pragma unroll
    for (int o = 16; o; o >>= 1) m = fmaxf(m, __shfl_xor_sync(0xffffffffu, m, o));
    if ((tid & 31) == 0) sred[tid >> 5] = m;
    __syncthreads();
    float mm = sred[0];
#pragma unroll
    for (int i = 1; i < 8; i++) mm = fmaxf(mm, sred[i]);
    __syncthreads();

    float s = 0.f;
    for (int v = tid; v < VVn; v += 256) s += __expf(row[v] - mm);
#pragma unroll
    for (int o = 16; o; o >>= 1) s += __shfl_xor_sync(0xffffffffu, s, o);
    if ((tid & 31) == 0) sred[tid >> 5] = s;
    __syncthreads();
    float ss = 0.f;
#pragma unroll
    for (int i = 0; i < 8; i++) ss += sred[i];

    float lse = mm + logf(ss);
    float* op = out + ((size_t)n * NSTEP + step) * VVn;
    for (int v = tid; v < VVn; v += 256) op[v] = row[v] - lse;
}

// ------------------------- launch -------------------------
extern "C" void kernel_launch(void* const* d_in, const int* in_sizes, int n_in,
                              void* d_out, int out_size)
{
    const int*   seq    = (const int*)  d_in[0];
    const float* query  = (const float*)d_in[1];
    const float* rp     = (const float*)d_in[2];
    const float* enc    = (const float*)d_in[3];
    const float* mask   = (const float*)d_in[4];
    const float* vrr    = (const float*)d_in[5];
    const float* embw   = (const float*)d_in[6];
    const float* logitw = (const float*)d_in[7];
    const float* logitb = (const float*)d_in[8];
    const float* valuew = (const float*)d_in[9];
    const float* valueb = (const float*)d_in[10];
    const float* offw   = (const float*)d_in[11];
    const float* offb   = (const float*)d_in[12];
    const float* aww    = (const float*)d_in[13];
    const float* awb    = (const float*)d_in[14];
    const float* ctxw   = (const float*)d_in[15];
    const float* ctxb   = (const float*)d_in[16];
    const float* hsw    = (const float*)d_in[17];
    const float* hsb    = (const float*)d_in[18];
    const float* alphaw = (const float*)d_in[19];
    const float* alphab = (const float*)d_in[20];
    const float* wih    = (const float*)d_in[21];
    const float* whh    = (const float*)d_in[22];
    float* out = (float*)d_out;

    float *p_value, *p_mixp, *p_gatesp, *p_logits, *p_hq, *p_xh, *p_h, *p_bigw, *p_gatew;
    cudaGetSymbolAddress((void**)&p_value,  g_value);
    cudaGetSymbolAddress((void**)&p_mixp,   g_mixp);
    cudaGetSymbolAddress((void**)&p_gatesp, g_gatesp);
    cudaGetSymbolAddress((void**)&p_logits, g_logits);
    cudaGetSymbolAddress((void**)&p_hq,     g_hq);
    cudaGetSymbolAddress((void**)&p_xh,     g_xh);
    cudaGetSymbolAddress((void**)&p_h,      g_h);
    cudaGetSymbolAddress((void**)&p_bigw,   g_bigw);
    cudaGetSymbolAddress((void**)&p_gatew,  g_gatew);

    // preamble
    build_bigw <<<1024, 256>>>(offw, aww, hsw, offb, awb, hsb);
    build_gatew<<<4096, 256>>>(wih, whh);
    init_state <<<NEq, 256>>>(query);
    // value = (enc @ value_w + b) * mask, scattered to [b][h][t][hd]
    gemm64<1><<<dim3(4, NB*TTn/64, 1), 256>>>(enc, DDim, valuew, DDim, valueb,
                                              p_value, DDim, DDim, 0, mask);

    for (int step = 0; step < NSTEP; step++) {
        // mix = [h|query] @ bigw  (split-K: 4 x 128)
        gemm64<0><<<dim3(8, 4, 4), 256>>>(p_hq, 512, p_bigw, 512, nullptr,
                                          p_mixp, 512, 128, NEq*512, nullptr);
        msda_step<<<NEq, 256>>>(rp, vrr, seq, embw, ctxw, ctxb, alphaw, alphab, step);
        // gates = [emb|attn|query|h] @ gatew (split-K: 4 x 256)
        gemm64<0><<<dim3(16, 4, 4), 256>>>(p_xh, 1024, p_gatew, 1024, nullptr,
                                           p_gatesp, 1024, 256, NEq*1024, nullptr);
        lstm_update<<<NEq, 256>>>();
        // logits = h2 @ logit_w + logit_b
        gemm64<0><<<dim3((VVn + 63)/64, 4, 1), 256>>>(p_h, DDim, logitw, VVn, logitb,
                                                      p_logits, VVn, DDim, 0, nullptr);
        logsoftmax_out<<<NEq, 256>>>(out, step);
    }
}

// round 3
// speedup vs baseline: 1.8267x; 1.8267x over previous
#include <cuda_runtime.h>
#include <cuda_bf16.h>
#include <math.h>
#include <stdint.h>

#define NB    8
#define NQd   32
#define NEq   256
#define SSq   21
#define NSTEP 20
#define DDim  256
#define HHn   8
#define HDn   32
#define LLn   4
#define PPn   4
#define VVn   10000
#define TTn   1920
#define VPAD  10112   // 79*128, padded N for logits weight

// ------------------------- device scratch (no allocation allowed) -------------------------
__device__ __align__(16) float g_value [NB*HHn*TTn*HDn];   // [b][h][t][hd]
__device__ __align__(16) float g_mixp  [4*NEq*512];        // split-K partials: off|aw|hbias
__device__ __align__(16) float g_gatesp[4*NEq*1024];       // split-K partials: gates
__device__ __align__(16) float g_logits[NEq*VVn];
__device__ __align__(16) float g_hq    [NEq*512];          // [h | query]
__device__ __align__(16) float g_xh    [NEq*1024];         // [emb | attn_res | query | h]
__device__ __align__(16) float g_h     [NEq*DDim];
__device__ __align__(16) float g_c     [NEq*DDim];
__device__ __align__(16) float g_bigb  [512];
// bf16 transposed weights [N][K]
__device__ __align__(16) __nv_bfloat16 g_bigwt  [512*512];
__device__ __align__(16) __nv_bfloat16 g_gatewt [1024*1024];
__device__ __align__(16) __nv_bfloat16 g_logitwt[VPAD*256];

__device__ __forceinline__ float tanha(float x) {
    float y;
    asm("tanh.approx.f32 %0, %1;" : "=f"(y) : "f"(x));
    return y;
}

__device__ __forceinline__ void mma16816(float* c, const uint32_t* a, const uint32_t* b) {
    asm volatile(
        "mma.sync.aligned.m16n8k16.row.col.f32.bf16.bf16.f32 "
        "{%0,%1,%2,%3}, {%4,%5,%6,%7}, {%8,%9}, {%0,%1,%2,%3};"
        : "+f"(c[0]), "+f"(c[1]), "+f"(c[2]), "+f"(c[3])
        : "r"(a[0]), "r"(a[1]), "r"(a[2]), "r"(a[3]), "r"(b[0]), "r"(b[1]));
}

__device__ __forceinline__ void cpasync16(uint32_t dst, const void* src) {
    asm volatile("cp.async.cg.shared.global [%0], [%1], 16;" :: "r"(dst), "l"(src));
}

// ------------------------- bf16 tensor-core GEMM -------------------------
// C[z*partStride + m*N + n] = sum_k A[m, kbeg+k] * Wt[n][kbeg+k] (+bias)
// A fp32 (converted to bf16 in smem), Wt bf16 [Npad][ldw] row-major (k contiguous).
// Block tile 64(M) x 128(N); 8 warps (2x4); warp tile 32x32. kChunk in {128, 256}.
__global__ __launch_bounds__(256)
void gemm_mma(const float* __restrict__ A, int lda,
              const __nv_bfloat16* __restrict__ Wt, int ldw,
              const float* __restrict__ bias,
              float* __restrict__ C, int N,
              int kChunk, int partStride)
{
    extern __shared__ char smem[];
    uint32_t* Asw = (uint32_t*)smem;                 // [64][SAW] words
    const int SAW = (kChunk >> 1) + 4;               // == 4 mod 32 -> conflict-free frags
    uint32_t* Bsw = (uint32_t*)(smem + 33792);       // [2][128][36] words

    const int tid  = threadIdx.x;
    const int lane = tid & 31, warp = tid >> 5;
    const int wm = warp >> 2, wn = warp & 3;
    const int g = lane >> 2, t = lane & 3;
    const int n0   = blockIdx.x * 128;
    const int row0 = blockIdx.y * 64;
    const int kbeg = blockIdx.z * kChunk;
    const int nk   = kChunk >> 4;

    // ---- load A tile (fp32 -> bf16) into smem ----
    for (int idx = tid * 4; idx < 64 * kChunk; idx += 1024) {
        int r = idx / kChunk, cc = idx - r * kChunk;
        float4 v = *(const float4*)(A + (size_t)(row0 + r) * lda + kbeg + cc);
        __nv_bfloat162 p0 = __float22bfloat162_rn(make_float2(v.x, v.y));
        __nv_bfloat162 p1 = __float22bfloat162_rn(make_float2(v.z, v.w));
        Asw[r * SAW + (cc >> 1)]     = *(uint32_t*)&p0;
        Asw[r * SAW + (cc >> 1) + 1] = *(uint32_t*)&p1;
    }

    // ---- B prefetch (cp.async, double buffered) ----
    const int bn = tid >> 1;                 // 0..127 : n row
    const int bq = (tid & 1) << 3;           // 0 or 8 : k offset
    const uint32_t bsm = (uint32_t)__cvta_generic_to_shared(Bsw);

    {
        const __nv_bfloat16* src = Wt + (size_t)(n0 + bn) * ldw + kbeg + bq;
        cpasync16(bsm + (uint32_t)((bn * 36 + (bq >> 1)) * 4), src);
        asm volatile("cp.async.commit_group;");
    }

    float acc[2][4][4];
#pragma unroll
    for (int i = 0; i < 2; i++)
#pragma unroll
        for (int j = 0; j < 4; j++)
#pragma unroll
            for (int q = 0; q < 4; q++) acc[i][j][q] = 0.f;

    for (int ks = 0; ks < nk; ks++) {
        __syncthreads();   // protect buffer (ks+1)&1 from readers of compute(ks-1); orders A STS
        if (ks + 1 < nk) {
            const __nv_bfloat16* src = Wt + (size_t)(n0 + bn) * ldw + kbeg + (ks + 1) * 16 + bq;
            cpasync16(bsm + (uint32_t)((((ks + 1) & 1) * 128 * 36 + bn * 36 + (bq >> 1)) * 4), src);
        }
        asm volatile("cp.async.commit_group;");
        asm volatile("cp.async.wait_group 1;");
        __syncthreads();

        uint32_t a[2][4];
#pragma unroll
        for (int mt = 0; mt < 2; mt++) {
            const uint32_t* ap = Asw + (wm * 32 + mt * 16 + g) * SAW + ks * 8 + t;
            a[mt][0] = ap[0];
            a[mt][1] = ap[8 * SAW];
            a[mt][2] = ap[4];
            a[mt][3] = ap[8 * SAW + 4];
        }
        const uint32_t* bbase = Bsw + (ks & 1) * 128 * 36;
        uint32_t bf[4][2];
#pragma unroll
        for (int nt = 0; nt < 4; nt++) {
            const uint32_t* bp = bbase + (wn * 32 + nt * 8 + g) * 36 + t;
            bf[nt][0] = bp[0];
            bf[nt][1] = bp[4];
        }
#pragma unroll
        for (int mt = 0; mt < 2; mt++)
#pragma unroll
            for (int nt = 0; nt < 4; nt++)
                mma16816(acc[mt][nt], a[mt], bf[nt]);
    }

    // ---- epilogue ----
    const size_t zb = (size_t)blockIdx.z * partStride;
#pragma unroll
    for (int mt = 0; mt < 2; mt++) {
        int m = row0 + wm * 32 + mt * 16 + g;
#pragma unroll
        for (int nt = 0; nt < 4; nt++) {
            int n = n0 + wn * 32 + nt * 8 + (t << 1);
            if (n < N) {
                float b0 = bias ? bias[n]     : 0.f;
                float b1 = bias ? bias[n + 1] : 0.f;
                float* c = acc[mt][nt];
                *(float2*)(C + zb + (size_t)m * N + n)       = make_float2(c[0] + b0, c[1] + b1);
                *(float2*)(C + zb + (size_t)(m + 8) * N + n) = make_float2(c[2] + b0, c[3] + b1);
            }
        }
    }
}

// ------------------------- fp32 GEMM kept for the one-time value build -------------------------
__global__ __launch_bounds__(256)
void gemm64_value(const float* __restrict__ A, const float* __restrict__ W,
                  const float* __restrict__ bias, float* __restrict__ C,
                  const float* __restrict__ mask)
{
    __shared__ float As[16*68];
    __shared__ float Bs[16*64];

    const int tid  = threadIdx.x;
    const int tx   = tid & 15;
    const int ty   = tid >> 4;
    const int col0 = blockIdx.x * 64;
    const int row0 = blockIdx.y * 64;

    float acc[4][4];
#pragma unroll
    for (int i = 0; i < 4; i++)
#pragma unroll
        for (int j = 0; j < 4; j++) acc[i][j] = 0.f;

    const int ar = tid >> 2;
    const int ak = (tid & 3) << 2;
    const int bk = tid >> 4;
    const int bc = (tid & 15) << 2;

    for (int k0 = 0; k0 < DDim; k0 += 16) {
        float4 av = *(const float4*)(A + (size_t)(row0 + ar) * DDim + (k0 + ak));
        As[(ak+0)*68 + ar] = av.x;
        As[(ak+1)*68 + ar] = av.y;
        As[(ak+2)*68 + ar] = av.z;
        As[(ak+3)*68 + ar] = av.w;
        *(float4*)(Bs + bk*64 + bc) = *(const float4*)(W + (size_t)(k0 + bk) * DDim + col0 + bc);
        __syncthreads();
#pragma unroll
        for (int k = 0; k < 16; k++) {
            float4 a = *(const float4*)(As + k*68 + (ty << 2));
            float4 b = *(const float4*)(Bs + k*64 + (tx << 2));
            float a4[4] = {a.x, a.y, a.z, a.w};
            float b4[4] = {b.x, b.y, b.z, b.w};
#pragma unroll
            for (int i = 0; i < 4; i++)
#pragma unroll
                for (int j = 0; j < 4; j++)
                    acc[i][j] = fmaf(a4[i], b4[j], acc[i][j]);
        }
        __syncthreads();
    }

#pragma unroll
    for (int i = 0; i < 4; i++) {
        int m  = row0 + (ty << 2) + i;
        int b  = m / TTn;
        int t  = m - b * TTn;
        float mk = mask[m];
#pragma unroll
        for (int j = 0; j < 4; j++) {
            int nc = col0 + (tx << 2) + j;
            int h  = nc >> 5, hd = nc & 31;
            g_value[(((size_t)(b*HHn + h))*TTn + t)*HDn + hd] = (acc[i][j] + bias[nc]) * mk;
        }
    }
}

// ------------------------- preamble kernels -------------------------
__global__ void build_bigwt(const float* __restrict__ offw, const float* __restrict__ aww,
                            const float* __restrict__ hsw,  const float* __restrict__ offb,
                            const float* __restrict__ awb,  const float* __restrict__ hsb)
{
    int i = blockIdx.x * 256 + threadIdx.x;     // 0 .. 512*512-1
    int n = i >> 9, k = i & 511;                // g_bigwt[n][k]
    float v;
    if (n < 128)      v = offw[k*128 + n];
    else if (n < 256) v = aww[k*128 + (n - 128)];
    else              v = (k < 256) ? hsw[k*256 + (n - 256)] : 0.f;
    g_bigwt[i] = __float2bfloat16(v);
    if (i < 512)
        g_bigb[i] = (i < 128) ? offb[i] : (i < 256) ? awb[i-128] : hsb[i-256];
}

__global__ void build_gatewt(const float* __restrict__ wih, const float* __restrict__ whh)
{
    int i = blockIdx.x * 256 + threadIdx.x;     // 0 .. 1024*1024-1
    int n = i >> 10, k = i & 1023;              // g_gatewt[n][k]
    float v = (k < 768) ? wih[k*1024 + n] : whh[(k - 768)*1024 + n];
    g_gatewt[i] = __float2bfloat16(v);
}

__global__ void build_logitwt(const float* __restrict__ lw)
{
    int i = blockIdx.x * 256 + threadIdx.x;     // 0 .. VPAD*256-1
    int k = i / VPAD, n = i - k * VPAD;         // coalesced read along n
    float v = (n < VVn) ? lw[(size_t)k * VVn + n] : 0.f;
    g_logitwt[(size_t)n * 256 + k] = __float2bfloat16(v);
}

__global__ void init_state(const float* __restrict__ query)
{
    int n = blockIdx.x, d = threadIdx.x;
    float q = query[n*DDim + d];
    g_h[n*DDim + d] = 0.f;
    g_c[n*DDim + d] = 0.f;
    g_hq[n*512 + d]        = 0.f;   // h slot
    g_hq[n*512 + 256 + d]  = q;     // query slot (static)
    g_xh[n*1024 + 512 + d] = q;     // query slot (static)
    g_xh[n*1024 + 768 + d] = 0.f;   // h slot
}

// ------------------------- fused MSDA + alpha + attn_res (block per query) -------------------------
__global__ __launch_bounds__(256)
void msda_step(const float* __restrict__ rp,     const float* __restrict__ vr,
               const int*   __restrict__ seq,    const float* __restrict__ embw,
               const float* __restrict__ ctxw,   const float* __restrict__ ctxb,
               const float* __restrict__ alphaw, const float* __restrict__ alphab,
               int step)
{
    __shared__ float s_hsamp[128*32];   // [h*16+lp][hd], aw-weighted samples
    __shared__ float s_hb[256];         // hbias + ctx_b
    __shared__ float s_off[128];
    __shared__ float s_aw[128];
    __shared__ float s_alpha[128];
    __shared__ float s_wgt[128];

    const int n    = blockIdx.x;
    const int b    = n >> 5;
    const int tid  = threadIdx.x;
    const int lane = tid & 31;
    const int w    = tid >> 5;

    // ---- phase A: emb write, gather split-K mix partials, aw softmax ----
    {
        int tok = (step == 0) ? 1 : seq[n*SSq + step - 1];
        g_xh[n*1024 + tid] = embw[(size_t)tok * DDim + tid];
    }
    {
        float s = 0.f;
#pragma unroll
        for (int z = 0; z < 4; z++) s += g_mixp[z*(NEq*512) + n*512 + 256 + tid];
        s_hb[tid] = s + g_bigb[256 + tid] + ctxb[tid];
    }
    if (tid < 128) {
        float so = 0.f, sa = 0.f;
#pragma unroll
        for (int z = 0; z < 4; z++) {
            so += g_mixp[z*(NEq*512) + n*512 + tid];
            sa += g_mixp[z*(NEq*512) + n*512 + 128 + tid];
        }
        so += g_bigb[tid];
        sa += g_bigb[128 + tid];
        s_off[tid] = so;
        float m = sa;
#pragma unroll
        for (int o = 8; o; o >>= 1) m = fmaxf(m, __shfl_xor_sync(0xffffffffu, m, o));
        float e = __expf(sa - m);
        float sm = e;
#pragma unroll
        for (int o = 8; o; o >>= 1) sm += __shfl_xor_sync(0xffffffffu, sm, o);
        s_aw[tid] = e / sm;
    }
    __syncthreads();

    // ---- phase B: bilinear sampling ----
    {
        const float rpn = rp[n];
#pragma unroll
        for (int i = 0; i < 16; i++) {
            int r = (w << 4) + i;
            int h = r >> 4;
            int l = (r >> 2) & 3;
            int shape_l = 1024 >> l;
            int start_l = 2048 - (2048 >> l);
            float refl = rpn * vr[b*LLn + l];
            float x = refl * (float)shape_l + s_off[r] - 0.5f;
            float x0f = floorf(x);
            float wf = x - x0f;
            int x0 = (int)x0f;
            const float* vbase = g_value + (((size_t)(b*HHn + h))*TTn + start_l) * HDn;
            float g0 = (x0 >= 0     && x0     < shape_l) ? vbase[(size_t)x0      * HDn + lane] : 0.f;
            float g1 = (x0 + 1 >= 0 && x0 + 1 < shape_l) ? vbase[(size_t)(x0+1) * HDn + lane] : 0.f;
            s_hsamp[r*32 + lane] = (g0 * (1.f - wf) + g1 * wf) * s_aw[r];
        }
    }
    __syncthreads();

    // ---- phase C: alpha[row] = sum_d tanh(hsamp_row.ctx[:,d] + hb[d]) * alpha_w[d] ----
    {
        const int d0 = lane << 3;
        float aw8[8];
#pragma unroll
        for (int j = 0; j < 8; j++) aw8[j] = __ldg(&alphaw[d0 + j]);
        const float ab = alphab[0];

#pragma unroll
        for (int pass = 0; pass < 2; pass++) {
            int r0 = (w << 4) + (pass << 3);
            float acc[8][8];
#pragma unroll
            for (int j = 0; j < 8; j++) {
                float base = s_hb[d0 + j];
#pragma unroll
                for (int i = 0; i < 8; i++) acc[i][j] = base;
            }
#pragma unroll 2
            for (int k = 0; k < 32; k++) {
                float4 c0 = __ldg((const float4*)(ctxw + k*DDim + d0));
                float4 c1 = __ldg((const float4*)(ctxw + k*DDim + d0 + 4));
                float cj[8] = {c0.x, c0.y, c0.z, c0.w, c1.x, c1.y, c1.z, c1.w};
#pragma unroll
                for (int i = 0; i < 8; i++) {
                    float a = s_hsamp[(r0 + i)*32 + k];
#pragma unroll
                    for (int j = 0; j < 8; j++) acc[i][j] = fmaf(a, cj[j], acc[i][j]);
                }
            }
#pragma unroll
            for (int i = 0; i < 8; i++) {
                float part = 0.f;
#pragma unroll
                for (int j = 0; j < 8; j++) part = fmaf(tanha(acc[i][j]), aw8[j], part);
#pragma unroll
                for (int o = 16; o; o >>= 1) part += __shfl_xor_sync(0xffffffffu, part, o);
                if (lane == 0) s_alpha[r0 + i] = part + ab;
            }
        }
    }
    __syncthreads();

    // ---- phase D: softmax over 16 per head ----
    if (tid < 128) {
        float v = s_alpha[tid];
        float m = v;
#pragma unroll
        for (int o = 8; o; o >>= 1) m = fmaxf(m, __shfl_xor_sync(0xffffffffu, m, o));
        float e = __expf(v - m);
        float sm = e;
#pragma unroll
        for (int o = 8; o; o >>= 1) sm += __shfl_xor_sync(0xffffffffu, sm, o);
        s_wgt[tid] = e / sm;
    }
    __syncthreads();

    // ---- phase E: attn_res ----
    {
        int h = tid >> 5, hd = tid & 31;
        float res = 0.f;
#pragma unroll
        for (int lp = 0; lp < 16; lp++)
            res = fmaf(s_wgt[(h << 4) + lp], s_hsamp[((h << 4) + lp)*32 + hd], res);
        g_xh[n*1024 + 256 + tid] = res;
    }
}

// ------------------------- LSTM cell update -------------------------
__global__ __launch_bounds__(256)
void lstm_update()
{
    int n = blockIdx.x, d = threadIdx.x;
    float gi = 0.f, gf = 0.f, gg = 0.f, go = 0.f;
#pragma unroll
    for (int z = 0; z < 4; z++) {
        const float* g = g_gatesp + (size_t)z*(NEq*1024) + n*1024;
        gi += g[d]; gf += g[256 + d]; gg += g[512 + d]; go += g[768 + d];
    }
    float c  = g_c[n*DDim + d];
    float sf = 1.f / (1.f + expf(-gf));
    float si = 1.f / (1.f + expf(-gi));
    float so = 1.f / (1.f + expf(-go));
    float c2 = sf * c + si * tanhf(gg);
    float h2 = so * tanhf(c2);
    g_c[n*DDim + d] = c2;
    g_h[n*DDim + d] = h2;
    g_hq[n*512 + d] = h2;
    g_xh[n*1024 + 768 + d] = h2;
}

// ------------------------- log-softmax (online single reduce pass) -------------------------
__global__ __launch_bounds__(256)
void logsoftmax_out(float* __restrict__ out, int step)
{
    __shared__ float sm_m[8], sm_s[8];
    const int n = blockIdx.x, tid = threadIdx.x;
    const float4* row4 = (const float4*)(g_logits + (size_t)n * VVn);

    float m = -1e30f, s = 0.f;
    for (int v = tid; v < VVn/4; v += 256) {
        float4 x = row4[v];
        float xm = fmaxf(fmaxf(x.x, x.y), fmaxf(x.z, x.w));
        if (xm > m) { s *= __expf(m - xm); m = xm; }
        s += __expf(x.x - m) + __expf(x.y - m) + __expf(x.z - m) + __expf(x.w - m);
    }
#pragma unroll
    for (int o = 16; o; o >>= 1) {
        float mo = __shfl_xor_sync(0xffffffffu, m, o);
        float so = __shfl_xor_sync(0xffffffffu, s, o);
        float mn = fmaxf(m, mo);
        s = s * __expf(m - mn) + so * __expf(mo - mn);
        m = mn;
    }
    if ((tid & 31) == 0) { sm_m[tid >> 5] = m; sm_s[tid >> 5] = s; }
    __syncthreads();
    float mm = -1e30f, ss = 0.f;
#pragma unroll
    for (int i = 0; i < 8; i++) {
        float mi = sm_m[i], si = sm_s[i];
        float mn = fmaxf(mm, mi);
        ss = ss * __expf(mm - mn) + si * __expf(mi - mn);
        mm = mn;
    }
    float lse = mm + logf(ss);

    float4* op = (float4*)(out + ((size_t)n * NSTEP + step) * VVn);
    for (int v = tid; v < VVn/4; v += 256) {
        float4 x = row4[v];
        op[v] = make_float4(x.x - lse, x.y - lse, x.z - lse, x.w - lse);
    }
}

// ------------------------- launch -------------------------
extern "C" void kernel_launch(void* const* d_in, const int* in_sizes, int n_in,
                              void* d_out, int out_size)
{
    const int*   seq    = (const int*)  d_in[0];
    const float* query  = (const float*)d_in[1];
    const float* rp     = (const float*)d_in[2];
    const float* enc    = (const float*)d_in[3];
    const float* mask   = (const float*)d_in[4];
    const float* vrr    = (const float*)d_in[5];
    const float* embw   = (const float*)d_in[6];
    const float* logitw = (const float*)d_in[7];
    const float* logitb = (const float*)d_in[8];
    const float* valuew = (const float*)d_in[9];
    const float* valueb = (const float*)d_in[10];
    const float* offw   = (const float*)d_in[11];
    const float* offb   = (const float*)d_in[12];
    const float* aww    = (const float*)d_in[13];
    const float* awb    = (const float*)d_in[14];
    const float* ctxw   = (const float*)d_in[15];
    const float* ctxb   = (const float*)d_in[16];
    const float* hsw    = (const float*)d_in[17];
    const float* hsb    = (const float*)d_in[18];
    const float* alphaw = (const float*)d_in[19];
    const float* alphab = (const float*)d_in[20];
    const float* wih    = (const float*)d_in[21];
    const float* whh    = (const float*)d_in[22];
    float* out = (float*)d_out;

    float *p_mixp, *p_gatesp, *p_logits, *p_hq, *p_xh, *p_h;
    __nv_bfloat16 *p_bigwt, *p_gatewt, *p_logitwt;
    cudaGetSymbolAddress((void**)&p_mixp,    g_mixp);
    cudaGetSymbolAddress((void**)&p_gatesp,  g_gatesp);
    cudaGetSymbolAddress((void**)&p_logits,  g_logits);
    cudaGetSymbolAddress((void**)&p_hq,      g_hq);
    cudaGetSymbolAddress((void**)&p_xh,      g_xh);
    cudaGetSymbolAddress((void**)&p_h,       g_h);
    cudaGetSymbolAddress((void**)&p_bigwt,   g_bigwt);
    cudaGetSymbolAddress((void**)&p_gatewt,  g_gatewt);
    cudaGetSymbolAddress((void**)&p_logitwt, g_logitwt);

    const int SMEM_MMA = 33792 + 2*128*36*4;   // 70656
    cudaFuncSetAttribute(gemm_mma, cudaFuncAttributeMaxDynamicSharedMemorySize, SMEM_MMA);

    // preamble
    build_bigwt  <<<1024, 256>>>(offw, aww, hsw, offb, awb, hsb);
    build_gatewt <<<4096, 256>>>(wih, whh);
    build_logitwt<<<VPAD, 256>>>(logitw);
    init_state   <<<NEq, 256>>>(query);
    gemm64_value <<<dim3(4, NB*TTn/64, 1), 256>>>(enc, valuew, valueb, nullptr, mask);

    for (int step = 0; step < NSTEP; step++) {
        // mix = [h|query](256x512) @ bigw(512x512)  — split-K 4 x 128
        gemm_mma<<<dim3(4, 4, 4), 256, SMEM_MMA>>>(p_hq, 512, p_bigwt, 512, nullptr,
                                                   p_mixp, 512, 128, NEq*512);
        msda_step<<<NEq, 256>>>(rp, vrr, seq, embw, ctxw, ctxb, alphaw, alphab, step);
        // gates = xh(256x1024) @ gatew(1024x1024) — split-K 4 x 256
        gemm_mma<<<dim3(8, 4, 4), 256, SMEM_MMA>>>(p_xh, 1024, p_gatewt, 1024, nullptr,
                                                   p_gatesp, 1024, 256, NEq*1024);
        lstm_update<<<NEq, 256>>>();
        // logits = h2(256x256) @ logit_w(256x10000) + b
        gemm_mma<<<dim3(VPAD/128, 4, 1), 256, SMEM_MMA>>>(p_h, 256, p_logitwt, 256, logitb,
                                                          p_logits, VVn, 256, 0);
        logsoftmax_out<<<NEq, 256>>>(out, step);
    }
}